// round 9
// baseline (speedup 1.0000x reference)
#include <cuda_runtime.h>

// NoQmix: q_tot[b] = sum_j agent_qs[b, j]
//
// Exact identity (verified R4/R6/R7, rel_err 1.7e-7): softmax(e, axis=1)
// sums to 1 per (b,j) column unconditionally, so q_tot[b] = sum_j qs[b,j].
// Only agent_qs (input 1, [4096, 64] fp32) matters: 1.05 MB read + 16 KB write.
//
// Measured model (R4/R6/R7): kernel time ~4.4-4.6us regardless of layout ->
// launch/ramp floor (T_ovh ~5000cyc), not data path. This round: halve the
// grid again (64 blocks x 256 threads), 8 rows/warp, 4 coalesced LDG.128
// per lane (MLP=4), 4 interleaved shuffle chains.

static constexpr int B_ROWS = 4096;
static constexpr int VECS = 16;       // float4 per row (64 floats)

__global__ void noqmix_rowsum_kernel(const float* __restrict__ qs,
                                     float* __restrict__ out) {
    const int gwarp = (blockIdx.x * blockDim.x + threadIdx.x) >> 5;
    const int lane  = threadIdx.x & 31;
    const int sub   = lane >> 4;      // which row of a pair
    const int slane = lane & 15;      // lane within 16-lane row group

    // Warp covers rows [gwarp*8, gwarp*8+8): four row-pairs.
    const int rbase = gwarp * 8 + sub;
    const float4* base = reinterpret_cast<const float4*>(qs);

    // 4 independent, fully coalesced LDG.128 per lane (MLP=4).
    float4 v0 = base[(size_t)(rbase + 0) * VECS + slane];
    float4 v1 = base[(size_t)(rbase + 2) * VECS + slane];
    float4 v2 = base[(size_t)(rbase + 4) * VECS + slane];
    float4 v3 = base[(size_t)(rbase + 6) * VECS + slane];

    float s0 = (v0.x + v0.y) + (v0.z + v0.w);
    float s1 = (v1.x + v1.y) + (v1.z + v1.w);
    float s2 = (v2.x + v2.y) + (v2.z + v2.w);
    float s3 = (v3.x + v3.y) + (v3.z + v3.w);

    // Four independent butterfly chains, interleaved by the scheduler.
#pragma unroll
    for (int off = 8; off > 0; off >>= 1) {
        s0 += __shfl_xor_sync(0xffffffffu, s0, off);
        s1 += __shfl_xor_sync(0xffffffffu, s1, off);
        s2 += __shfl_xor_sync(0xffffffffu, s2, off);
        s3 += __shfl_xor_sync(0xffffffffu, s3, off);
    }

    if (slane == 0) {
        out[rbase + 0] = s0;
        out[rbase + 2] = s1;
        out[rbase + 4] = s2;
        out[rbase + 6] = s3;
    }
}

extern "C" void kernel_launch(void* const* d_in, const int* in_sizes, int n_in,
                              void* d_out, int out_size) {
    // Input order: features(0), agent_qs(1), adj(2), states(3), W(4), a(5).
    const float* agent_qs = (const float*)d_in[1];
    float* out = (float*)d_out;

    // 4096 rows, 8 rows/warp, 8 warps/block -> 64 rows/block -> 64 blocks.
    const int threads = 256;
    const int rows_per_block = (threads / 32) * 8;          // 64
    const int blocks = B_ROWS / rows_per_block;              // 64 (exact)
    noqmix_rowsum_kernel<<<blocks, threads>>>(agent_qs, out);
}